// round 1
// baseline (speedup 1.0000x reference)
#include <cuda_runtime.h>

// Inverse 2x2 Haar wavelet transform.
// Input  x: [4B, C, H, W] fp32, quadrants k=0..3 at offset k*B*C*H*W
// Output  : [B, C, 2H, 2W] fp32
//
// out[b,c,2i+0,2j+0] = 0.5*(x1 - x2 - x3 + x4)
// out[b,c,2i+0,2j+1] = 0.5*(x1 + x2 - x3 - x4)
// out[b,c,2i+1,2j+0] = 0.5*(x1 - x2 + x3 - x4)
// out[b,c,2i+1,2j+1] = 0.5*(x1 + x2 + x3 + x4)
//
// Each thread: 4 consecutive j of one (b,c,i) row.
//   loads : 4 x float4 (16B each, one per quadrant)
//   stores: 4 x float4 (two per output row)

#ifndef IWT_B
#define IWT_B 32
#endif

static constexpr int H = 128;
static constexpr int W = 128;
static constexpr int W4 = W / 4;              // float4 groups per input row
static constexpr long long PLANE_IN  = (long long)H * W;        // 16384
static constexpr long long PLANE_OUT = (long long)(2*H) * (2*W); // 65536

__global__ __launch_bounds__(256)
void iwt_kernel(const float* __restrict__ x, float* __restrict__ out,
                long long quad_stride,   // B*C*H*W elements between quadrants
                int n_threads)           // planes * H * W4
{
    int tid = blockIdx.x * blockDim.x + threadIdx.x;
    if (tid >= n_threads) return;

    // tid -> (plane, i, j4)
    int j4    = tid & (W4 - 1);          // W4 = 32, power of 2
    int rest  = tid >> 5;                // /W4
    int i     = rest & (H - 1);          // H = 128, power of 2
    int plane = rest >> 7;               // /H

    long long in_off = (long long)plane * PLANE_IN + (long long)i * W + (long long)j4 * 4;

    const float4 a = __ldg((const float4*)(x + in_off));                    // x1
    const float4 b = __ldg((const float4*)(x + in_off + quad_stride));      // x2
    const float4 c = __ldg((const float4*)(x + in_off + 2 * quad_stride));  // x3
    const float4 d = __ldg((const float4*)(x + in_off + 3 * quad_stride));  // x4

    // butterfly per lane, scaled by 0.5
    float e00[4], e01[4], e10[4], e11[4];
    {
        const float ax[4] = {a.x, a.y, a.z, a.w};
        const float bx[4] = {b.x, b.y, b.z, b.w};
        const float cx[4] = {c.x, c.y, c.z, c.w};
        const float dx[4] = {d.x, d.y, d.z, d.w};
        #pragma unroll
        for (int l = 0; l < 4; l++) {
            float s_ad = ax[l] + dx[l];   // x1 + x4
            float d_ad = ax[l] - dx[l];   // x1 - x4
            float s_bc = bx[l] + cx[l];   // x2 + x3
            float d_bc = bx[l] - cx[l];   // x2 - x3
            e00[l] = 0.5f * (s_ad - s_bc);   // x1 - x2 - x3 + x4
            e01[l] = 0.5f * (d_ad + d_bc);   // x1 + x2 - x3 - x4
            e10[l] = 0.5f * (d_ad - d_bc);   // x1 - x2 + x3 - x4
            e11[l] = 0.5f * (s_ad + s_bc);   // x1 + x2 + x3 + x4
        }
    }

    // output: rows 2i and 2i+1, cols 8*j4 .. 8*j4+7 (8 floats per row = 2 float4)
    long long out_base = (long long)plane * PLANE_OUT
                       + (long long)(2 * i) * (2 * W)
                       + (long long)j4 * 8;

    float4 r0a = make_float4(e00[0], e01[0], e00[1], e01[1]);
    float4 r0b = make_float4(e00[2], e01[2], e00[3], e01[3]);
    float4 r1a = make_float4(e10[0], e11[0], e10[1], e11[1]);
    float4 r1b = make_float4(e10[2], e11[2], e10[3], e11[3]);

    *(float4*)(out + out_base)               = r0a;
    *(float4*)(out + out_base + 4)           = r0b;
    *(float4*)(out + out_base + 2 * W)       = r1a;
    *(float4*)(out + out_base + 2 * W + 4)   = r1b;
}

extern "C" void kernel_launch(void* const* d_in, const int* in_sizes, int n_in,
                              void* d_out, int out_size) {
    const float* x = (const float*)d_in[0];
    float* out = (float*)d_out;

    // in_sizes[0] = 4B*C*H*W; quadrant stride = total/4
    long long total = (long long)in_sizes[0];
    long long quad_stride = total / 4;

    // planes = B*C = quad_stride / (H*W)
    long long planes = quad_stride / PLANE_IN;
    int n_threads = (int)(planes * H * W4);

    int block = 256;
    int grid = (n_threads + block - 1) / block;
    iwt_kernel<<<grid, block>>>(x, out, quad_stride, n_threads);
}